// round 3
// baseline (speedup 1.0000x reference)
#include <cuda_runtime.h>
#include <cstdint>

// out[b,o,n] = sum_{k,c} in[b,c,n] * W[o,k,c] * attn[b,k,n]
// B=8, C_IN=16, C_OUT=16, K=4, N=524288  (all fp32)
//
// Compute-bound in scalar fp32 (~4.56G FMA). Packed fma.rn.f32x2
// (sm_103a, PTX-only lowering to FFMA2) doubles FMA throughput.
// Weights pre-duplicated {w,w} in shared so one LDS.128 broadcast
// yields two packed multiplier operands with no per-FMA pack ops.

#define BB   8
#define CIN  16
#define COUT 16
#define KK   4
#define TPB  256
#define NPT  4

typedef unsigned long long u64;

__device__ __forceinline__ u64 pack2(float lo, float hi) {
    u64 r;
    asm("mov.b64 %0, {%1, %2};" : "=l"(r) : "f"(lo), "f"(hi));
    return r;
}
__device__ __forceinline__ void unpack2(u64 v, float& lo, float& hi) {
    asm("mov.b64 {%0, %1}, %2;" : "=f"(lo), "=f"(hi) : "l"(v));
}
__device__ __forceinline__ u64 mul2(u64 a, u64 b) {
    u64 d;
    asm("mul.rn.f32x2 %0, %1, %2;" : "=l"(d) : "l"(a), "l"(b));
    return d;
}
__device__ __forceinline__ u64 fma2(u64 a, u64 b, u64 c) {
    u64 d;
    asm("fma.rn.f32x2 %0, %1, %2, %3;" : "=l"(d) : "l"(a), "l"(b), "l"(c));
    return d;
}

__global__ __launch_bounds__(TPB, 2)
void tconv_kernel(const float* __restrict__ in,
                  const float* __restrict__ wgt,
                  const float* __restrict__ attn,
                  float* __restrict__ out, int N) {
    // Weights duplicated as {w,w} pairs, layout [c][k][o]: the o-loop reads
    // consecutive 16B chunks (LDS.128 broadcast, conflict-free).
    // __align__(16) is required: ulonglong2 LDS.128 to an 8-aligned address traps.
    __shared__ __align__(16) u64 ws[CIN * KK * COUT];

    const int tid = threadIdx.x;
    for (int i = tid; i < CIN * KK * COUT; i += TPB) {
        int o = i & 15;
        int k = (i >> 4) & 3;
        int c = i >> 6;
        float v = wgt[(o * KK + k) * CIN + c];   // weight[o][k][c]
        ws[i] = pack2(v, v);
    }
    __syncthreads();

    const int b  = blockIdx.y;
    const int n0 = (blockIdx.x * TPB + tid) * NPT;
    if (n0 >= N) return;
    const int stride4 = N >> 2;

    const float4* inp = reinterpret_cast<const float4*>(in   + (size_t)b * CIN * N) + (n0 >> 2);
    const float4* atp = reinterpret_cast<const float4*>(attn + (size_t)b * KK  * N) + (n0 >> 2);

    // attention taps for these 4 n positions, packed as 2x f32x2
    u64 at[KK][2];
    #pragma unroll
    for (int k = 0; k < KK; k++) {
        float4 a = atp[k * stride4];
        at[k][0] = pack2(a.x, a.y);
        at[k][1] = pack2(a.z, a.w);
    }

    u64 acc[COUT][2];
    #pragma unroll
    for (int o = 0; o < COUT; o++) { acc[o][0] = 0ull; acc[o][1] = 0ull; }

    #pragma unroll 4
    for (int c = 0; c < CIN; c++) {
        float4 x4 = inp[c * stride4];
        u64 x0 = pack2(x4.x, x4.y);
        u64 x1 = pack2(x4.z, x4.w);
        #pragma unroll
        for (int k = 0; k < KK; k++) {
            u64 xa0 = mul2(x0, at[k][0]);
            u64 xa1 = mul2(x1, at[k][1]);
            const ulonglong2* wrow =
                reinterpret_cast<const ulonglong2*>(&ws[(c * KK + k) * COUT]);
            #pragma unroll
            for (int o2 = 0; o2 < COUT / 2; o2++) {
                ulonglong2 w2 = wrow[o2];   // LDS.128 broadcast: 2 packed weights
                acc[2 * o2    ][0] = fma2(w2.x, xa0, acc[2 * o2    ][0]);
                acc[2 * o2    ][1] = fma2(w2.x, xa1, acc[2 * o2    ][1]);
                acc[2 * o2 + 1][0] = fma2(w2.y, xa0, acc[2 * o2 + 1][0]);
                acc[2 * o2 + 1][1] = fma2(w2.y, xa1, acc[2 * o2 + 1][1]);
            }
        }
    }

    float4* outp = reinterpret_cast<float4*>(out + (size_t)b * COUT * N) + (n0 >> 2);
    #pragma unroll
    for (int o = 0; o < COUT; o++) {
        float4 r;
        unpack2(acc[o][0], r.x, r.y);
        unpack2(acc[o][1], r.z, r.w);
        outp[o * stride4] = r;
    }
}

extern "C" void kernel_launch(void* const* d_in, const int* in_sizes, int n_in,
                              void* d_out, int out_size) {
    const float* in   = (const float*)d_in[0];   // (B, C_IN, N)
    const float* wgt  = (const float*)d_in[1];   // (C_OUT, K, C_IN)
    const float* attn = (const float*)d_in[2];   // (B, K, N)
    float* out = (float*)d_out;                  // (B, C_OUT, N)

    int N = in_sizes[0] / (BB * CIN);            // 524288
    dim3 grid((N + TPB * NPT - 1) / (TPB * NPT), BB);
    tconv_kernel<<<grid, TPB>>>(in, wgt, attn, out, N);
}

// round 9
// speedup vs baseline: 1.1645x; 1.1645x over previous
#include <cuda_runtime.h>
#include <cstdint>

// out[b,o,n] = sum_{k,c} in[b,c,n] * W[o,k,c] * attn[b,k,n]
// B=8, C_IN=16, C_OUT=16, K=4, N=524288  (all fp32)
//
// R3 profile: fma=56%, issue=43%, occ=23%, regs=128. Gap to the fma-pipe
// floor == one exposed DRAM LDG per c-iteration (serialized load->use).
// Fix: unconditional 1-deep prefetch (clamped row index, no predicate so
// ptxas keeps the LDG at block top) + attn LDGs hoisted above the
// weight-smem fill/barrier. Packed fma.rn.f32x2 throughout.

#define BB   8
#define CIN  16
#define COUT 16
#define KK   4
#define TPB  256
#define NPT  4

typedef unsigned long long u64;

__device__ __forceinline__ u64 pack2(float lo, float hi) {
    u64 r;
    asm("mov.b64 %0, {%1, %2};" : "=l"(r) : "f"(lo), "f"(hi));
    return r;
}
__device__ __forceinline__ void unpack2(u64 v, float& lo, float& hi) {
    asm("mov.b64 {%0, %1}, %2;" : "=f"(lo), "=f"(hi) : "l"(v));
}
__device__ __forceinline__ u64 mul2(u64 a, u64 b) {
    u64 d;
    asm("mul.rn.f32x2 %0, %1, %2;" : "=l"(d) : "l"(a), "l"(b));
    return d;
}
__device__ __forceinline__ u64 fma2(u64 a, u64 b, u64 c) {
    u64 d;
    asm("fma.rn.f32x2 %0, %1, %2, %3;" : "=l"(d) : "l"(a), "l"(b), "l"(c));
    return d;
}

__global__ __launch_bounds__(TPB, 2)
void tconv_kernel(const float* __restrict__ in,
                  const float* __restrict__ wgt,
                  const float* __restrict__ attn,
                  float* __restrict__ out, int N) {
    // Weights duplicated as {w,w} pairs, layout [c][k][o]: the o-loop reads
    // consecutive 16B chunks (LDS.128 broadcast, conflict-free).
    __shared__ __align__(16) u64 ws[CIN * KK * COUT];

    const int tid = threadIdx.x;
    const int b   = blockIdx.y;
    const int n0  = (blockIdx.x * TPB + tid) * NPT;
    const unsigned stride4 = (unsigned)(N >> 2);      // float4 row stride
    const unsigned base4   = (unsigned)(n0 >> 2);

    // 32-bit element offsets into float4 views (arrays < 256MB, safe).
    const float4* inp = reinterpret_cast<const float4*>(in)   + (unsigned)b * CIN * stride4 + base4;
    const float4* atp = reinterpret_cast<const float4*>(attn) + (unsigned)b * KK  * stride4 + base4;

    // Attn loads issue FIRST: latency overlaps the smem fill + barrier.
    float4 a0 = atp[0];
    float4 a1 = atp[stride4];
    float4 a2 = atp[2 * stride4];
    float4 a3 = atp[3 * stride4];
    float4 cur = inp[0];               // prefetch first input row

    for (int i = tid; i < CIN * KK * COUT; i += TPB) {
        int o = i & 15;
        int k = (i >> 4) & 3;
        int c = i >> 6;
        float v = wgt[(o * KK + k) * CIN + c];   // weight[o][k][c]
        ws[i] = pack2(v, v);
    }
    __syncthreads();

    u64 at[KK][2];
    at[0][0] = pack2(a0.x, a0.y);  at[0][1] = pack2(a0.z, a0.w);
    at[1][0] = pack2(a1.x, a1.y);  at[1][1] = pack2(a1.z, a1.w);
    at[2][0] = pack2(a2.x, a2.y);  at[2][1] = pack2(a2.z, a2.w);
    at[3][0] = pack2(a3.x, a3.y);  at[3][1] = pack2(a3.z, a3.w);

    u64 acc[COUT][2];
    #pragma unroll
    for (int o = 0; o < COUT; o++) { acc[o][0] = 0ull; acc[o][1] = 0ull; }

    #pragma unroll
    for (int c = 0; c < CIN; c++) {
        // Unconditional 1-deep prefetch: clamped index keeps it branch- and
        // predicate-free so the LDG issues at the top of the unrolled block,
        // hiding DRAM latency under this iteration's ~1152 SMSP pipe-cycles.
        int cn = (c + 1 < CIN) ? (c + 1) : (CIN - 1);
        float4 nxt = inp[cn * stride4];
        u64 x0 = pack2(cur.x, cur.y);
        u64 x1 = pack2(cur.z, cur.w);
        #pragma unroll
        for (int k = 0; k < KK; k++) {
            u64 xa0 = mul2(x0, at[k][0]);
            u64 xa1 = mul2(x1, at[k][1]);
            const ulonglong2* wrow =
                reinterpret_cast<const ulonglong2*>(&ws[(c * KK + k) * COUT]);
            #pragma unroll
            for (int o2 = 0; o2 < COUT / 2; o2++) {
                ulonglong2 w2 = wrow[o2];   // LDS.128 broadcast: 2 packed weights
                acc[2 * o2    ][0] = fma2(w2.x, xa0, acc[2 * o2    ][0]);
                acc[2 * o2    ][1] = fma2(w2.x, xa1, acc[2 * o2    ][1]);
                acc[2 * o2 + 1][0] = fma2(w2.y, xa0, acc[2 * o2 + 1][0]);
                acc[2 * o2 + 1][1] = fma2(w2.y, xa1, acc[2 * o2 + 1][1]);
            }
        }
        cur = nxt;
    }

    float4* outp = reinterpret_cast<float4*>(out) + (unsigned)b * COUT * stride4 + base4;
    #pragma unroll
    for (int o = 0; o < COUT; o++) {
        float4 r;
        unpack2(acc[o][0], r.x, r.y);
        unpack2(acc[o][1], r.z, r.w);
        outp[o * stride4] = r;
    }
}

extern "C" void kernel_launch(void* const* d_in, const int* in_sizes, int n_in,
                              void* d_out, int out_size) {
    const float* in   = (const float*)d_in[0];   // (B, C_IN, N)
    const float* wgt  = (const float*)d_in[1];   // (C_OUT, K, C_IN)
    const float* attn = (const float*)d_in[2];   // (B, K, N)
    float* out = (float*)d_out;                  // (B, C_OUT, N)

    int N = in_sizes[0] / (BB * CIN);            // 524288
    dim3 grid(N / (TPB * NPT), BB);
    tconv_kernel<<<grid, TPB>>>(in, wgt, attn, out, N);
}